// round 8
// baseline (speedup 1.0000x reference)
#include <cuda_runtime.h>
#include <cuda_bf16.h>
#include <math.h>
#include <stdint.h>

#define NN 32768
#define EE 524288
#define FF 32
#define HH 512
#define CC 10
#define GG 64

typedef __nv_bfloat16 bf16;

// ---------------- scratch ----------------------------------------------------
// per-buffer planes: hi (bf16, GEMM term1 A), pk (fp8 pairs [hi8, loS8], GEMM cross A),
// hl (packed bf16x2 [hi|lo], exact h for agg/pool). cols 0..511 = h, 512..1023 = agg.
__device__ __align__(128) bf16     g_A1hi[NN * 1024];
__device__ __align__(128) bf16     g_A2hi[NN * 1024];
__device__ __align__(128) uint8_t  g_A1pk[NN * 2048];
__device__ __align__(128) uint8_t  g_A2pk[NN * 2048];
__device__ __align__(128) uint32_t g_A1hl[NN * 1024];
__device__ __align__(128) uint32_t g_A2hl[NN * 1024];
__device__ __align__(128) bf16     g_A0hi[NN * 128];
__device__ __align__(128) uint8_t  g_A0pk[NN * 256];
__device__ __align__(128) bf16     g_B0hi[HH * 128];
__device__ __align__(128) uint8_t  g_B0pk[HH * 256];
__device__ __align__(128) bf16     g_Bhi[4 * HH * 1024];
__device__ __align__(128) uint8_t  g_Bpk[4 * HH * 2048];
__device__ int   g_rowptr[NN + 1];
__device__ int   g_cursor[NN];
__device__ int   g_cnt[NN];
__device__ int   g_colsrc[EE];
__device__ int   g_grow[GG + 1];
__device__ int   g_gcnt[GG];
__device__ float g_feat[GG * 2 * HH];
__device__ float g_m1[GG * HH];
__device__ float g_m2[GG * HH];

#define SCL 512.0f
#define ISCL (1.0f / 512.0f)

// ---------------- helpers ----------------------------------------------------
__device__ __forceinline__ uint32_t smem_u32(const void* p) {
    uint32_t r;
    asm("{ .reg .u64 t; cvta.to.shared.u64 t, %1; cvt.u32.u64 %0, t; }" : "=r"(r) : "l"(p));
    return r;
}
__device__ __forceinline__ void cpa16(uint32_t d, const void* s) {
    asm volatile("cp.async.cg.shared.global [%0], [%1], 16;" :: "r"(d), "l"(s));
}
#define CP_COMMIT() asm volatile("cp.async.commit_group;" ::: "memory")
__device__ __forceinline__ void ldsm4(uint32_t* r, uint32_t a) {
    asm volatile("ldmatrix.sync.aligned.m8n8.x4.shared.b16 {%0,%1,%2,%3}, [%4];"
                 : "=r"(r[0]), "=r"(r[1]), "=r"(r[2]), "=r"(r[3]) : "r"(a));
}
__device__ __forceinline__ void mma_bf16(float* c, const uint32_t* a, const uint32_t* b) {
    asm volatile("mma.sync.aligned.m16n8k16.row.col.f32.bf16.bf16.f32 "
                 "{%0,%1,%2,%3}, {%4,%5,%6,%7}, {%8,%9}, {%0,%1,%2,%3};"
                 : "+f"(c[0]), "+f"(c[1]), "+f"(c[2]), "+f"(c[3])
                 : "r"(a[0]), "r"(a[1]), "r"(a[2]), "r"(a[3]), "r"(b[0]), "r"(b[1]));
}
__device__ __forceinline__ void mma_fp8(float* c, const uint32_t* a, const uint32_t* b) {
    asm volatile("mma.sync.aligned.m16n8k32.row.col.f32.e4m3.e4m3.f32 "
                 "{%0,%1,%2,%3}, {%4,%5,%6,%7}, {%8,%9}, {%0,%1,%2,%3};"
                 : "+f"(c[0]), "+f"(c[1]), "+f"(c[2]), "+f"(c[3])
                 : "r"(a[0]), "r"(a[1]), "r"(a[2]), "r"(a[3]), "r"(b[0]), "r"(b[1]));
}
__device__ __forceinline__ void split_bf16(float v, bf16& hi, bf16& lo) {
    hi = __float2bfloat16_rn(v);
    lo = __float2bfloat16_rn(v - __bfloat162float(hi));
}
// pack one element for the fp8-cross plane: byte0 = e4m3(hi), byte1 = e4m3(lo*512)
__device__ __forceinline__ uint16_t pk8(float hi, float lo) {
    uint16_t r;
    asm("cvt.rn.satfinite.e4m3x2.f32 %0, %1, %2;" : "=h"(r) : "f"(lo * SCL), "f"(hi));
    return r;
}
// pack bf16x2 [hi|lo] (hi in low half)
__device__ __forceinline__ uint32_t pkhl(bf16 hi, bf16 lo) {
    __nv_bfloat162 t; t.x = hi; t.y = lo;
    return *(uint32_t*)&t;
}
__device__ __forceinline__ float unhl(uint32_t p) {
    __nv_bfloat162 t = *(__nv_bfloat162*)&p;
    float2 f = __bfloat1622float2(t);
    return f.x + f.y;
}
__device__ __forceinline__ uint32_t swz(uint32_t off) { return off ^ ((off >> 3) & 0x70); }

// ---------------- CSR build --------------------------------------------------
__global__ void k_zero_counts() {
    int i = blockIdx.x * blockDim.x + threadIdx.x;
    if (i < NN) g_cnt[i] = 0;
    if (i < GG) g_gcnt[i] = 0;
}
__global__ void k_hist(const int* __restrict__ ei, const int* __restrict__ batch) {
    int e = blockIdx.x * blockDim.x + threadIdx.x;
    if (e < EE) atomicAdd(&g_cnt[ei[EE + e]], 1);
    if (e < NN) atomicAdd(&g_gcnt[batch[e]], 1);
}
__global__ void k_scan() {
    __shared__ int sums[1024];
    const int per = NN / 1024;
    int tid = threadIdx.x, base = tid * per;
    int local[32];
    int s = 0;
    for (int i = 0; i < per; i++) { local[i] = s; s += g_cnt[base + i]; }
    sums[tid] = s;
    __syncthreads();
    for (int off = 1; off < 1024; off <<= 1) {
        int v = (tid >= off) ? sums[tid - off] : 0;
        __syncthreads();
        sums[tid] += v;
        __syncthreads();
    }
    int excl = (tid == 0) ? 0 : sums[tid - 1];
    for (int i = 0; i < per; i++) {
        int v = excl + local[i];
        g_rowptr[base + i] = v;
        g_cursor[base + i] = v;
    }
    if (tid == 1023) g_rowptr[NN] = sums[1023];
    if (tid == 0) {
        int t = 0;
        for (int g = 0; g < GG; g++) { g_grow[g] = t; t += g_gcnt[g]; }
        g_grow[GG] = t;
    }
}
__global__ void k_fill(const int* __restrict__ ei) {
    int e = blockIdx.x * blockDim.x + threadIdx.x;
    if (e >= EE) return;
    int p = atomicAdd(&g_cursor[ei[EE + e]], 1);
    g_colsrc[p] = ei[e];
}
__global__ void k_sortadj() {
    int v = blockIdx.x * blockDim.x + threadIdx.x;
    if (v >= NN) return;
    int s = g_rowptr[v], e = g_rowptr[v + 1];
    for (int i = s + 1; i < e; i++) {
        int key = g_colsrc[i];
        int j = i - 1;
        while (j >= s && g_colsrc[j] > key) { g_colsrc[j + 1] = g_colsrc[j]; j--; }
        g_colsrc[j + 1] = key;
    }
}

// ---------------- split prep -------------------------------------------------
__global__ void k_split_x(const float* __restrict__ x) {
    int i = blockIdx.x * blockDim.x + threadIdx.x;
    if (i >= NN * 64) return;
    int r = i >> 6, k = i & 63;
    float v = (k < FF) ? x[r * FF + k] : 0.f;
    bf16 hi, lo;
    split_bf16(v, hi, lo);
    g_A0hi[r * 128 + k] = hi;
    ((uint16_t*)g_A0pk)[r * 128 + k] = pk8(__bfloat162float(hi), __bfloat162float(lo));
}
__global__ void k_split_w0(const float* __restrict__ wr, const float* __restrict__ ws) {
    int i = blockIdx.x * blockDim.x + threadIdx.x;
    if (i >= HH * 128) return;
    int n = i >> 7, k = i & 127;
    float v = 0.f;
    if (k < FF) v = wr[k * HH + n];
    else if (k >= 64 && k < 64 + FF) v = ws[(k - 64) * HH + n];
    bf16 hi, lo;
    split_bf16(v, hi, lo);
    g_B0hi[i] = hi;
    // weight pk: byte0 = e4m3(lo*S), byte1 = e4m3(hi)
    uint16_t p;
    asm("cvt.rn.satfinite.e4m3x2.f32 %0, %1, %2;" : "=h"(p)
        : "f"(__bfloat162float(hi)), "f"(__bfloat162float(lo) * SCL));
    ((uint16_t*)g_B0pk)[i] = p;
}
__global__ void k_split_w(const float* __restrict__ wr, const float* __restrict__ ws) {
    int i = blockIdx.x * blockDim.x + threadIdx.x;
    if (i >= 4 * HH * 1024) return;
    int l = i >> 19;
    int rem = i & ((1 << 19) - 1);
    int n = rem >> 10, k = rem & 1023;
    float v = (k < HH) ? wr[(size_t)l * HH * HH + (size_t)k * HH + n]
                       : ws[(size_t)l * HH * HH + (size_t)(k - HH) * HH + n];
    bf16 hi, lo;
    split_bf16(v, hi, lo);
    g_Bhi[i] = hi;
    uint16_t p;
    asm("cvt.rn.satfinite.e4m3x2.f32 %0, %1, %2;" : "=h"(p)
        : "f"(__bfloat162float(hi)), "f"(__bfloat162float(lo) * SCL));
    ((uint16_t*)g_Bpk)[i] = p;
}

// ---------------- aggregation ------------------------------------------------
__global__ void k_agg32(const float* __restrict__ x) {
    int v = blockIdx.x * 4 + threadIdx.y;
    int lane = threadIdx.x;
    if (v >= NN) return;
    int s = g_rowptr[v], e = g_rowptr[v + 1];
    float acc = 0.f;
    for (int i = s; i < e; i++) acc += x[g_colsrc[i] * FF + lane];
    bf16 hi, lo;
    split_bf16(acc, hi, lo);
    g_A0hi[v * 128 + 64 + lane] = hi;
    ((uint16_t*)g_A0pk)[v * 128 + 64 + lane] = pk8(__bfloat162float(hi), __bfloat162float(lo));
    g_A0hi[v * 128 + 96 + lane] = __float2bfloat16(0.f);
    ((uint16_t*)g_A0pk)[v * 128 + 96 + lane] = 0;
}
// gather packed h (cols 0..511) -> write agg into cols 512..1023 of all planes
__global__ void k_agg512(uint32_t* __restrict__ phl, bf16* __restrict__ phi,
                         uint8_t* __restrict__ ppk) {
    int v = blockIdx.x, tx = threadIdx.x;
    int s = g_rowptr[v], e = g_rowptr[v + 1];
    float acc[4] = {0.f, 0.f, 0.f, 0.f};
    for (int i = s; i < e; i++) {
        const uint4 t = *(const uint4*)&phl[(size_t)g_colsrc[i] * 1024 + tx * 4];
        acc[0] += unhl(t.x);
        acc[1] += unhl(t.y);
        acc[2] += unhl(t.z);
        acc[3] += unhl(t.w);
    }
    uint4 outhl;
    bf16 hi[4], lo[4];
    uint16_t pk[4];
#pragma unroll
    for (int j = 0; j < 4; j++) {
        split_bf16(acc[j], hi[j], lo[j]);
        pk[j] = pk8(__bfloat162float(hi[j]), __bfloat162float(lo[j]));
    }
    outhl.x = pkhl(hi[0], lo[0]);
    outhl.y = pkhl(hi[1], lo[1]);
    outhl.z = pkhl(hi[2], lo[2]);
    outhl.w = pkhl(hi[3], lo[3]);
    *(uint4*)&phl[(size_t)v * 1024 + 512 + tx * 4] = outhl;
    *(uint2*)&phi[(size_t)v * 1024 + 512 + tx * 4] = *(uint2*)hi;
    *(uint2*)&((uint16_t*)ppk)[(size_t)v * 1024 + 512 + tx * 4] = *(uint2*)pk;
}

// ---------------- mma GEMM: bf16 term1 + fp8 cross ---------------------------
// CTA 128m x 128n, 8 warps (2x4), warp tile 64x32, BK=64, 2-stage, occ 1.
// stage 64KB: sAhi 16K | sBhi 16K | sApk 16K | sBpk 16K.
// D = Ahi@Bhi (bf16) + (1/S)*(Apk@Bpk) (fp8: ahi*bloS + aloS*bhi).
#define STAGE_B 65536

__global__ __launch_bounds__(256, 1)
void k_mmagemm(const bf16* __restrict__ Ahi, const uint8_t* __restrict__ Apk,
               const bf16* __restrict__ Bhi, const uint8_t* __restrict__ Bpk,
               const float* __restrict__ bias,
               bf16* __restrict__ ohi, uint8_t* __restrict__ opk,
               uint32_t* __restrict__ ohl, int Kp) {
    extern __shared__ char smem[];
    uint32_t sb = smem_u32(smem);
    const int tid = threadIdx.x;
    const int wid = tid >> 5, lane = tid & 31;
    const int brow = blockIdx.y * 128;
    const int bcol = blockIdx.x * 128;
    const int wm = (wid & 1) * 64;
    const int wn = (wid >> 1) * 32;
    const int C = Kp >> 6;
    const int Kp2 = Kp * 2;

    float acc[4][4][4], acc2[4][4][4];
#pragma unroll
    for (int i = 0; i < 4; i++)
#pragma unroll
        for (int j = 0; j < 4; j++)
#pragma unroll
            for (int q = 0; q < 4; q++) { acc[i][j][q] = 0.f; acc2[i][j][q] = 0.f; }

    auto copy_stage = [&](int buf, int c) {
        uint32_t st = sb + (uint32_t)buf * STAGE_B;
#pragma unroll
        for (int i = 0; i < 4; i++) {
            int id = tid * 4 + i;
            int r = id >> 3, u = id & 7;
            uint32_t sw = swz((uint32_t)(r * 128 + u * 16));
            cpa16(st + sw, Ahi + (size_t)(brow + r) * Kp + c * 64 + u * 8);
            cpa16(st + 16384 + sw, Bhi + (size_t)(bcol + r) * Kp + c * 64 + u * 8);
            cpa16(st + 32768 + sw, Apk + (size_t)(brow + r) * Kp2 + c * 128 + u * 16);
            cpa16(st + 49152 + sw, Bpk + (size_t)(bcol + r) * Kp2 + c * 128 + u * 16);
        }
        CP_COMMIT();
    };

    const int a_row = wm + ((lane >> 3) & 1) * 8 + (lane & 7);
    const int a_ub  = lane >> 4;
    const int b_row = wn + ((lane >> 4) & 1) * 8 + (lane & 7);
    const int b_ub  = (lane >> 3) & 1;

    copy_stage(0, 0);

    for (int c = 0; c < C; c++) {
        int buf = c & 1;
        if (c + 1 < C) {
            copy_stage(buf ^ 1, c + 1);
            asm volatile("cp.async.wait_group 1;" ::: "memory");
        } else {
            asm volatile("cp.async.wait_group 0;" ::: "memory");
        }
        __syncthreads();

        uint32_t base = sb + (uint32_t)buf * STAGE_B;
        // term1: bf16
#pragma unroll
        for (int ks = 0; ks < 4; ks++) {
            int ku = ks * 2;
            uint32_t ah[4][4], bh[2][4];
#pragma unroll
            for (int i = 0; i < 4; i++)
                ldsm4(ah[i], base + swz((uint32_t)((a_row + i * 16) * 128 + (ku + a_ub) * 16)));
#pragma unroll
            for (int g = 0; g < 2; g++)
                ldsm4(bh[g], base + 16384 + swz((uint32_t)((b_row + g * 16) * 128 + (ku + b_ub) * 16)));
#pragma unroll
            for (int i = 0; i < 4; i++)
#pragma unroll
                for (int j = 0; j < 4; j++)
                    mma_bf16(acc[i][j], ah[i], &bh[j >> 1][(j & 1) * 2]);
        }
        // cross: fp8 (identical addressing; fp8-pair == b16 element footprint)
#pragma unroll
        for (int ks = 0; ks < 4; ks++) {
            int ku = ks * 2;
            uint32_t af[4][4], bf_[2][4];
#pragma unroll
            for (int i = 0; i < 4; i++)
                ldsm4(af[i], base + 32768 + swz((uint32_t)((a_row + i * 16) * 128 + (ku + a_ub) * 16)));
#pragma unroll
            for (int g = 0; g < 2; g++)
                ldsm4(bf_[g], base + 49152 + swz((uint32_t)((b_row + g * 16) * 128 + (ku + b_ub) * 16)));
#pragma unroll
            for (int i = 0; i < 4; i++)
#pragma unroll
                for (int j = 0; j < 4; j++)
                    mma_fp8(acc2[i][j], af[i], &bf_[j >> 1][(j & 1) * 2]);
        }
        __syncthreads();
    }

    // epilogue: D = acc + acc2/S + bias -> tanh -> hi/pk/hl planes (cols 0..511)
#pragma unroll
    for (int i = 0; i < 4; i++) {
        int r0 = brow + wm + i * 16 + (lane >> 2);
#pragma unroll
        for (int j = 0; j < 4; j++) {
            int col = bcol + wn + j * 8 + (lane & 3) * 2;
            float b0v = bias[col], b1v = bias[col + 1];
            float v0 = tanhf(acc[i][j][0] + acc2[i][j][0] * ISCL + b0v);
            float v1 = tanhf(acc[i][j][1] + acc2[i][j][1] * ISCL + b1v);
            float v2 = tanhf(acc[i][j][2] + acc2[i][j][2] * ISCL + b0v);
            float v3 = tanhf(acc[i][j][3] + acc2[i][j][3] * ISCL + b1v);
            bf16 h0, l0, h1, l1;
            split_bf16(v0, h0, l0); split_bf16(v1, h1, l1);
            {
                __nv_bfloat162 th; th.x = h0; th.y = h1;
                *(__nv_bfloat162*)&ohi[(size_t)r0 * 1024 + col] = th;
                uint2 hl; hl.x = pkhl(h0, l0); hl.y = pkhl(h1, l1);
                *(uint2*)&ohl[(size_t)r0 * 1024 + col] = hl;
                uint32_t pk = (uint32_t)pk8(__bfloat162float(h0), __bfloat162float(l0)) |
                              ((uint32_t)pk8(__bfloat162float(h1), __bfloat162float(l1)) << 16);
                *(uint32_t*)&((uint16_t*)opk)[(size_t)r0 * 1024 + col] = pk;
            }
            split_bf16(v2, h0, l0); split_bf16(v3, h1, l1);
            {
                __nv_bfloat162 th; th.x = h0; th.y = h1;
                *(__nv_bfloat162*)&ohi[(size_t)(r0 + 8) * 1024 + col] = th;
                uint2 hl; hl.x = pkhl(h0, l0); hl.y = pkhl(h1, l1);
                *(uint2*)&ohl[(size_t)(r0 + 8) * 1024 + col] = hl;
                uint32_t pk = (uint32_t)pk8(__bfloat162float(h0), __bfloat162float(l0)) |
                              ((uint32_t)pk8(__bfloat162float(h1), __bfloat162float(l1)) << 16);
                *(uint32_t*)&((uint16_t*)opk)[(size_t)(r0 + 8) * 1024 + col] = pk;
            }
        }
    }
}

// ---------------- pooling / MLP / head ---------------------------------------
__global__ void k_pool(const uint32_t* __restrict__ hl) {
    int g = blockIdx.x;
    int c0 = threadIdx.x * 4;  // 128 threads x 4 cols = 512
    int s = g_grow[g], e = g_grow[g + 1];
    float mx[4] = {-INFINITY, -INFINITY, -INFINITY, -INFINITY};
    float sm[4] = {0.f, 0.f, 0.f, 0.f};
    for (int i = s; i < e; i++) {
        const uint4 t = *(const uint4*)&hl[(size_t)i * 1024 + c0];
        float v0 = unhl(t.x), v1 = unhl(t.y), v2 = unhl(t.z), v3 = unhl(t.w);
        mx[0] = fmaxf(mx[0], v0); sm[0] += v0;
        mx[1] = fmaxf(mx[1], v1); sm[1] += v1;
        mx[2] = fmaxf(mx[2], v2); sm[2] += v2;
        mx[3] = fmaxf(mx[3], v3); sm[3] += v3;
    }
    float inv = 1.f / fmaxf((float)(e - s), 1.f);
#pragma unroll
    for (int q = 0; q < 4; q++) {
        g_feat[g * 2 * HH + c0 + q]      = mx[q];
        g_feat[g * 2 * HH + HH + c0 + q] = sm[q] * inv;
    }
}
__global__ void k_mlp(const float* __restrict__ A, const float* __restrict__ W,
                      const float* __restrict__ b, float* __restrict__ out,
                      int K, int Nn) {
    int n = blockIdx.x * blockDim.x + threadIdx.x;
    int m = blockIdx.y;
    float s = b[n];
    for (int k = 0; k < K; k++) s += A[m * K + k] * W[k * Nn + n];
    out[m * Nn + n] = tanhf(s);
}
__global__ void k_head(const float* __restrict__ A, const float* __restrict__ W,
                       const float* __restrict__ b, float* __restrict__ out) {
    int g = blockIdx.x;
    int lane = threadIdx.x;
    float cls[CC];
#pragma unroll
    for (int c = 0; c < CC; c++) {
        float s = 0.f;
        for (int k = lane; k < HH; k += 32) s += A[g * HH + k] * W[k * CC + c];
#pragma unroll
        for (int off = 16; off; off >>= 1) s += __shfl_xor_sync(0xffffffffu, s, off);
        cls[c] = s + b[c];
    }
    float mx = -INFINITY;
#pragma unroll
    for (int c = 0; c < CC; c++) mx = fmaxf(mx, cls[c]);
    float se = 0.f;
#pragma unroll
    for (int c = 0; c < CC; c++) se += expf(cls[c] - mx);
    float lse = mx + logf(se);
    if (lane < CC) out[g * CC + lane] = cls[lane] - lse;
}

// ---------------- launcher ---------------------------------------------------
extern "C" void kernel_launch(void* const* d_in, const int* in_sizes, int n_in,
                              void* d_out, int out_size) {
    const float* x       = (const float*)d_in[0];
    const int*   ei      = (const int*)  d_in[1];
    const int*   batch   = (const int*)  d_in[2];
    const float* w_root0 = (const float*)d_in[3];
    const float* w_rel0  = (const float*)d_in[4];
    const float* b0      = (const float*)d_in[5];
    const float* w_root  = (const float*)d_in[6];
    const float* w_rel   = (const float*)d_in[7];
    const float* bb      = (const float*)d_in[8];
    const float* lin1_w  = (const float*)d_in[9];
    const float* lin1_b  = (const float*)d_in[10];
    const float* lin2_w  = (const float*)d_in[11];
    const float* lin2_b  = (const float*)d_in[12];
    const float* lin3_w  = (const float*)d_in[13];
    const float* lin3_b  = (const float*)d_in[14];
    float* out = (float*)d_out;

    float *feat, *m1, *m2;
    bf16 *a0h, *b0h, *a1h, *a2h, *bh;
    uint8_t *a0p, *b0p, *a1p, *a2p, *bp;
    uint32_t *a1l, *a2l;
    cudaGetSymbolAddress((void**)&feat, g_feat);
    cudaGetSymbolAddress((void**)&m1, g_m1);
    cudaGetSymbolAddress((void**)&m2, g_m2);
    cudaGetSymbolAddress((void**)&a0h, g_A0hi);
    cudaGetSymbolAddress((void**)&a0p, g_A0pk);
    cudaGetSymbolAddress((void**)&a1h, g_A1hi);
    cudaGetSymbolAddress((void**)&a1p, g_A1pk);
    cudaGetSymbolAddress((void**)&a1l, g_A1hl);
    cudaGetSymbolAddress((void**)&a2h, g_A2hi);
    cudaGetSymbolAddress((void**)&a2p, g_A2pk);
    cudaGetSymbolAddress((void**)&a2l, g_A2hl);
    cudaGetSymbolAddress((void**)&b0h, g_B0hi);
    cudaGetSymbolAddress((void**)&b0p, g_B0pk);
    cudaGetSymbolAddress((void**)&bh, g_Bhi);
    cudaGetSymbolAddress((void**)&bp, g_Bpk);

    cudaFuncSetAttribute(k_mmagemm, cudaFuncAttributeMaxDynamicSharedMemorySize,
                         2 * STAGE_B);
    const int dynsmem = 2 * STAGE_B;

    // CSR + graph segments
    k_zero_counts<<<(NN + 255) / 256, 256>>>();
    k_hist<<<(EE + 255) / 256, 256>>>(ei, batch);
    k_scan<<<1, 1024>>>();
    k_fill<<<(EE + 255) / 256, 256>>>(ei);
    k_sortadj<<<(NN + 127) / 128, 128>>>();

    // prep splits
    k_split_x<<<(NN * 64 + 255) / 256, 256>>>(x);
    k_split_w0<<<(HH * 128 + 255) / 256, 256>>>(w_root0, w_rel0);
    k_split_w<<<(4 * HH * 1024 + 255) / 256, 256>>>(w_root, w_rel);

    // layer 0: K'=128 -> writes buf1 cols 0..511
    k_agg32<<<NN / 4, dim3(32, 4)>>>(x);
    k_mmagemm<<<dim3(HH / 128, NN / 128), 256, dynsmem>>>(
        a0h, a0p, b0h, b0p, b0, a1h, a1p, a1l, 128);

    // layers 1..4: K'=1024, ping-pong buf1/buf2
    bf16 *chh = a1h, *nhh = a2h;
    uint8_t *chp = a1p, *nhp = a2p;
    uint32_t *chl = a1l, *nhl = a2l;
    for (int l = 0; l < 4; l++) {
        k_agg512<<<NN, 128>>>(chl, chh, chp);
        k_mmagemm<<<dim3(HH / 128, NN / 128), 256, dynsmem>>>(
            chh, chp, bh + (size_t)l * HH * 1024, bp + (size_t)l * HH * 2048,
            bb + l * HH, nhh, nhp, nhl, 1024);
        bf16* t1 = chh; chh = nhh; nhh = t1;
        uint8_t* t2 = chp; chp = nhp; nhp = t2;
        uint32_t* t3 = chl; chl = nhl; nhl = t3;
    }

    k_pool<<<GG, 128>>>(chl);
    k_mlp<<<dim3(HH / 128, GG), 128>>>(feat, lin1_w, lin1_b, m1, 2 * HH, HH);
    k_mlp<<<dim3(HH / 128, GG), 128>>>(m1, lin2_w, lin2_b, m2, HH, HH);
    k_head<<<GG, 32>>>(m2, lin3_w, lin3_b, out);
}